// round 9
// baseline (speedup 1.0000x reference)
#include <cuda_runtime.h>

#define NN 100000
#define FF 128
#define HH 128
#define ZZ 64
#define EE 1600000
#define EPOS 200000
#define NCHUNK ((NN + 255) / 256)   // 391

// ---- scratch (static device globals) ----
__device__ __align__(16) int   g_cnt[NN];          // dst histogram (no self-loop)
__device__ __align__(16) int   g_bsum[512];
__device__ __align__(16) int   g_boff[512];
__device__ __align__(16) int   g_rowstart[NN + 1];
__device__ __align__(16) int   g_cursor[NN];
__device__ __align__(16) int   g_csr[EE];          // src ids sorted by dst
__device__ __align__(16) float g_dinv[NN];
__device__ __align__(16) float g_hs1[NN * HH];     // (x@W1)*dinv[row]
__device__ __align__(16) float g_h[NN * HH];       // relu output
__device__ __align__(16) float g_hs2[NN * ZZ];     // (h@W2)*dinv[row]
__device__ __align__(16) float g_lat[NN * ZZ];     // latent

// ---------------- histogram / dinv ----------------
__global__ void cnt_init_k() {
    int i = blockIdx.x * blockDim.x + threadIdx.x;
    if (i < NN) g_cnt[i] = 0;
}

__global__ void cnt_count_k(const int* __restrict__ ei) {
    int e = blockIdx.x * blockDim.x + threadIdx.x;
    if (e < EE) atomicAdd(&g_cnt[ei[EE + e]], 1);
}

__global__ void dinv_k() {
    int i = blockIdx.x * blockDim.x + threadIdx.x;
    if (i < NN) g_dinv[i] = rsqrtf((float)(g_cnt[i] + 1));  // +1 self-loop
}

// ---------------- scan (3 small kernels) ----------------
__global__ void scan_bsum_k() {
    __shared__ int sh[256];
    int i = blockIdx.x * 256 + threadIdx.x;
    sh[threadIdx.x] = (i < NN) ? g_cnt[i] : 0;
    __syncthreads();
    for (int o = 128; o > 0; o >>= 1) {
        if (threadIdx.x < o) sh[threadIdx.x] += sh[threadIdx.x + o];
        __syncthreads();
    }
    if (threadIdx.x == 0) g_bsum[blockIdx.x] = sh[0];
}

__global__ void scan_boff_k() {  // 1 block, 512 threads; exclusive scan of g_bsum
    __shared__ int sh[512];
    int t = threadIdx.x;
    int v = (t < NCHUNK) ? g_bsum[t] : 0;
    sh[t] = v;
    __syncthreads();
    for (int o = 1; o < 512; o <<= 1) {
        int add = (t >= o) ? sh[t - o] : 0;
        __syncthreads();
        sh[t] += add;
        __syncthreads();
    }
    g_boff[t] = sh[t] - v;  // exclusive
}

__global__ void scan_final_k() {
    __shared__ int sh[256];
    int t = threadIdx.x;
    int i = blockIdx.x * 256 + t;
    int v = (i < NN) ? g_cnt[i] : 0;
    sh[t] = v;
    __syncthreads();
    for (int o = 1; o < 256; o <<= 1) {
        int add = (t >= o) ? sh[t - o] : 0;
        __syncthreads();
        sh[t] += add;
        __syncthreads();
    }
    if (i < NN) {
        int rs = g_boff[blockIdx.x] + sh[t] - v;  // exclusive
        g_rowstart[i] = rs;
        g_cursor[i] = rs;
        if (i == NN - 1) g_rowstart[NN] = EE;
    }
}

__global__ void csr_fill_k(const int* __restrict__ ei) {
    int e = blockIdx.x * blockDim.x + threadIdx.x;
    if (e < EE) {
        int dst = ei[EE + e];
        int pos = atomicAdd(&g_cursor[dst], 1);
        g_csr[pos] = ei[e];
    }
}

// ---------------- GEMM: out = (X @ W) * dinv[row], software-pipelined ----------------
// Block tile: 64 rows x NC cols, 256 threads, per-thread 8 rows x (NC/32) cols.
// Next k-block's X/W fragments prefetched into registers during current compute.
template <int NC>
__device__ __forceinline__ void gemm_body(const float* __restrict__ X,
                                          const float* __restrict__ W,
                                          float* __restrict__ out) {
    constexpr int CPT = NC / 32;
    __shared__ __align__(16) float Xs[64 * 32];
    __shared__ __align__(16) float Ws[32 * NC];

    const int tid = threadIdx.x;
    const int tx = tid & 31;
    const int ty = tid >> 5;
    const int row0 = blockIdx.x * 64;

    float acc[8][CPT];
#pragma unroll
    for (int i = 0; i < 8; i++)
#pragma unroll
        for (int j = 0; j < CPT; j++) acc[i][j] = 0.0f;

    // register staging for prefetch
    float xr[8];
    float4 wr[CPT];

    // prefetch k-block 0
#pragma unroll
    for (int i = 0; i < 8; i++) {
        int gr = row0 + ty + i * 8;
        xr[i] = (gr < NN) ? X[(long)gr * FF + tx] : 0.0f;
    }
#pragma unroll
    for (int i = 0; i < CPT; i++) {
        int idx = (tid + i * 256) * 4;
        int kk = idx / NC;
        int c = idx % NC;
        wr[i] = *(const float4*)&W[(long)kk * NC + c];
    }

    for (int kb = 0; kb < FF; kb += 32) {
        // commit staged fragments to smem
#pragma unroll
        for (int i = 0; i < 8; i++) Xs[(ty + i * 8) * 32 + tx] = xr[i];
#pragma unroll
        for (int i = 0; i < CPT; i++) {
            int idx = (tid + i * 256) * 4;
            int kk = idx / NC;
            int c = idx % NC;
            *(float4*)&Ws[kk * NC + c] = wr[i];
        }
        __syncthreads();

        // prefetch next k-block while computing this one
        if (kb + 32 < FF) {
#pragma unroll
            for (int i = 0; i < 8; i++) {
                int gr = row0 + ty + i * 8;
                xr[i] = (gr < NN) ? X[(long)gr * FF + (kb + 32) + tx] : 0.0f;
            }
#pragma unroll
            for (int i = 0; i < CPT; i++) {
                int idx = (tid + i * 256) * 4;
                int kk = idx / NC;
                int c = idx % NC;
                wr[i] = *(const float4*)&W[(long)(kb + 32 + kk) * NC + c];
            }
        }

#pragma unroll
        for (int kk = 0; kk < 32; kk++) {
            float b[CPT];
            if (CPT == 4) {
                float4 t = *(const float4*)&Ws[kk * NC + tx * 4];
                b[0] = t.x; b[1] = t.y; b[2] = t.z; b[3] = t.w;
            } else {
                float2 t = *(const float2*)&Ws[kk * NC + tx * 2];
                b[0] = t.x; b[1] = t.y;
            }
            float a[8];
#pragma unroll
            for (int i = 0; i < 8; i++) a[i] = Xs[(ty * 8 + i) * 32 + kk];
#pragma unroll
            for (int i = 0; i < 8; i++)
#pragma unroll
                for (int j = 0; j < CPT; j++) acc[i][j] = fmaf(a[i], b[j], acc[i][j]);
        }
        __syncthreads();
    }
#pragma unroll
    for (int i = 0; i < 8; i++) {
        int gr = row0 + ty * 8 + i;
        if (gr < NN) {
            float s = g_dinv[gr];
#pragma unroll
            for (int j = 0; j < CPT; j++) out[(long)gr * NC + tx * CPT + j] = acc[i][j] * s;
        }
    }
}

__global__ void gemm1_k(const float* __restrict__ x, const float* __restrict__ W1) {
    gemm_body<HH>(x, W1, g_hs1);
}
__global__ void gemm2_k(const float* __restrict__ W2) {
    gemm_body<ZZ>(g_h, W2, g_hs2);
}

// ---------------- gather: one warp per dst node, register accumulation ----------------
__global__ void gather1_k(const float* __restrict__ b1) {
    int gt = blockIdx.x * blockDim.x + threadIdx.x;
    int n = gt >> 5;
    int lane = gt & 31;
    if (n >= NN) return;
    int s = g_rowstart[n];
    int e = g_rowstart[n + 1];

    float4 acc = *(const float4*)&g_hs1[(long)n * 128 + lane * 4];  // self-loop

    for (int base = s; base < e; base += 32) {
        int idx = base + lane;
        int myi = (idx < e) ? g_csr[idx] : 0;
        int cnt = min(32, e - base);
        int j = 0;
        for (; j + 8 <= cnt; j += 8) {
            int ss[8];
#pragma unroll
            for (int q = 0; q < 8; q++) ss[q] = __shfl_sync(0xffffffffu, myi, j + q);
            float4 vv[8];
#pragma unroll
            for (int q = 0; q < 8; q++)
                vv[q] = *(const float4*)&g_hs1[(long)ss[q] * 128 + lane * 4];
#pragma unroll
            for (int q = 0; q < 8; q++) {
                acc.x += vv[q].x;
                acc.y += vv[q].y;
                acc.z += vv[q].z;
                acc.w += vv[q].w;
            }
        }
        for (; j < cnt; j++) {
            int s0 = __shfl_sync(0xffffffffu, myi, j);
            float4 v = *(const float4*)&g_hs1[(long)s0 * 128 + lane * 4];
            acc.x += v.x; acc.y += v.y; acc.z += v.z; acc.w += v.w;
        }
    }
    float d = g_dinv[n];
    float4 bb = *(const float4*)&b1[lane * 4];
    float4 o;
    o.x = fmaxf(fmaf(d, acc.x, bb.x), 0.0f);
    o.y = fmaxf(fmaf(d, acc.y, bb.y), 0.0f);
    o.z = fmaxf(fmaf(d, acc.z, bb.z), 0.0f);
    o.w = fmaxf(fmaf(d, acc.w, bb.w), 0.0f);
    *(float4*)&g_h[(long)n * 128 + lane * 4] = o;
}

__global__ void gather2_k(const float* __restrict__ b2) {
    int gt = blockIdx.x * blockDim.x + threadIdx.x;
    int n = gt >> 5;
    int lane = gt & 31;
    if (n >= NN) return;
    int s = g_rowstart[n];
    int e = g_rowstart[n + 1];

    float2 acc = *(const float2*)&g_hs2[(long)n * 64 + lane * 2];  // self-loop

    for (int base = s; base < e; base += 32) {
        int idx = base + lane;
        int myi = (idx < e) ? g_csr[idx] : 0;
        int cnt = min(32, e - base);
        int j = 0;
        for (; j + 8 <= cnt; j += 8) {
            int ss[8];
#pragma unroll
            for (int q = 0; q < 8; q++) ss[q] = __shfl_sync(0xffffffffu, myi, j + q);
            float2 vv[8];
#pragma unroll
            for (int q = 0; q < 8; q++)
                vv[q] = *(const float2*)&g_hs2[(long)ss[q] * 64 + lane * 2];
#pragma unroll
            for (int q = 0; q < 8; q++) {
                acc.x += vv[q].x;
                acc.y += vv[q].y;
            }
        }
        for (; j < cnt; j++) {
            int s0 = __shfl_sync(0xffffffffu, myi, j);
            float2 v = *(const float2*)&g_hs2[(long)s0 * 64 + lane * 2];
            acc.x += v.x; acc.y += v.y;
        }
    }
    float d = g_dinv[n];
    float2 bb = *(const float2*)&b2[lane * 2];
    float2 o;
    o.x = fmaf(d, acc.x, bb.x);
    o.y = fmaf(d, acc.y, bb.y);
    *(float2*)&g_lat[(long)n * 64 + lane * 2] = o;
}

// ---------------- decoder: one warp per edge pair ----------------
__global__ void decode_k(const int* __restrict__ pe,
                         const int* __restrict__ ne,
                         float* __restrict__ out) {
    int gt = blockIdx.x * blockDim.x + threadIdx.x;
    int w = gt >> 5;
    int lane = gt & 31;
    if (w >= 2 * EPOS) return;
    int a, b;
    if (w < EPOS) {
        a = pe[w];
        b = pe[EPOS + w];
    } else {
        int k = w - EPOS;
        a = ne[k];
        b = ne[EPOS + k];
    }
    float2 u = *(const float2*)&g_lat[(long)a * 64 + lane * 2];
    float2 v = *(const float2*)&g_lat[(long)b * 64 + lane * 2];
    float s = u.x * v.x + u.y * v.y;
#pragma unroll
    for (int o = 16; o > 0; o >>= 1) s += __shfl_xor_sync(0xffffffffu, s, o);
    if (lane == 0) out[w] = s;
}

// ---------------- launch (single stream) ----------------
extern "C" void kernel_launch(void* const* d_in, const int* in_sizes, int n_in,
                              void* d_out, int out_size) {
    const float* x = (const float*)d_in[0];
    const float* W1 = (const float*)d_in[1];
    const float* b1 = (const float*)d_in[2];
    const float* W2 = (const float*)d_in[3];
    const float* b2 = (const float*)d_in[4];
    const int* ei = (const int*)d_in[5];
    const int* pe = (const int*)d_in[6];
    const int* ne = (const int*)d_in[7];
    float* out = (float*)d_out;

    // CSR build + dinv
    cnt_init_k<<<(NN + 255) / 256, 256>>>();
    cnt_count_k<<<(EE + 255) / 256, 256>>>(ei);
    dinv_k<<<(NN + 255) / 256, 256>>>();
    scan_bsum_k<<<NCHUNK, 256>>>();
    scan_boff_k<<<1, 512>>>();
    scan_final_k<<<NCHUNK, 256>>>();
    csr_fill_k<<<(EE + 255) / 256, 256>>>(ei);

    // layer 1
    gemm1_k<<<(NN + 63) / 64, 256>>>(x, W1);
    gather1_k<<<(NN * 32 + 255) / 256, 256>>>(b1);

    // layer 2
    gemm2_k<<<(NN + 63) / 64, 256>>>(W2);
    gather2_k<<<(NN * 32 + 255) / 256, 256>>>(b2);

    decode_k<<<(2 * EPOS * 32 + 255) / 256, 256>>>(pe, ne, out);
}

// round 10
// speedup vs baseline: 1.0371x; 1.0371x over previous
#include <cuda_runtime.h>

#define NN 100000
#define FF 128
#define HH 128
#define ZZ 64
#define EE 1600000
#define EPOS 200000
#define NCHUNK ((NN + 255) / 256)   // 391

// ---- scratch (static device globals) ----
__device__ __align__(16) int   g_cnt[NN];          // dst histogram (no self-loop)
__device__ __align__(16) int   g_bsum[512];
__device__ __align__(16) int   g_boff[512];
__device__ __align__(16) int   g_rowstart[NN + 1];
__device__ __align__(16) int   g_cursor[NN];
__device__ __align__(16) int   g_csr[EE];          // src ids sorted by dst
__device__ __align__(16) float g_dinv[NN];
__device__ __align__(16) float g_hs1[NN * HH];     // (x@W1)*dinv[row]
__device__ __align__(16) float g_h[NN * HH];       // relu output
__device__ __align__(16) float g_hs2[NN * ZZ];     // (h@W2)*dinv[row]
__device__ __align__(16) float g_lat[NN * ZZ];     // latent

// ---- packed f32x2 helpers (sm_103a FFMA2) ----
__device__ __forceinline__ unsigned long long pk2(float x, float y) {
    unsigned long long r;
    asm("mov.b64 %0, {%1, %2};" : "=l"(r) : "f"(x), "f"(y));
    return r;
}
__device__ __forceinline__ void fma2(unsigned long long& d,
                                     unsigned long long a,
                                     unsigned long long b) {
    asm("fma.rn.f32x2 %0, %1, %2, %0;" : "+l"(d) : "l"(a), "l"(b));
}
__device__ __forceinline__ float2 unpk2(unsigned long long v) {
    float x, y;
    asm("mov.b64 {%0, %1}, %2;" : "=f"(x), "=f"(y) : "l"(v));
    return make_float2(x, y);
}

// ---------------- histogram / dinv ----------------
__global__ void cnt_init_k() {
    int i = blockIdx.x * blockDim.x + threadIdx.x;
    if (i < NN) g_cnt[i] = 0;
}

__global__ void cnt_count_k(const int* __restrict__ ei) {
    int e = blockIdx.x * blockDim.x + threadIdx.x;
    if (e < EE) atomicAdd(&g_cnt[ei[EE + e]], 1);
}

__global__ void dinv_k() {
    int i = blockIdx.x * blockDim.x + threadIdx.x;
    if (i < NN) g_dinv[i] = rsqrtf((float)(g_cnt[i] + 1));  // +1 self-loop
}

// ---------------- scan (3 small kernels) ----------------
__global__ void scan_bsum_k() {
    __shared__ int sh[256];
    int i = blockIdx.x * 256 + threadIdx.x;
    sh[threadIdx.x] = (i < NN) ? g_cnt[i] : 0;
    __syncthreads();
    for (int o = 128; o > 0; o >>= 1) {
        if (threadIdx.x < o) sh[threadIdx.x] += sh[threadIdx.x + o];
        __syncthreads();
    }
    if (threadIdx.x == 0) g_bsum[blockIdx.x] = sh[0];
}

__global__ void scan_boff_k() {  // 1 block, 512 threads; exclusive scan of g_bsum
    __shared__ int sh[512];
    int t = threadIdx.x;
    int v = (t < NCHUNK) ? g_bsum[t] : 0;
    sh[t] = v;
    __syncthreads();
    for (int o = 1; o < 512; o <<= 1) {
        int add = (t >= o) ? sh[t - o] : 0;
        __syncthreads();
        sh[t] += add;
        __syncthreads();
    }
    g_boff[t] = sh[t] - v;  // exclusive
}

__global__ void scan_final_k() {
    __shared__ int sh[256];
    int t = threadIdx.x;
    int i = blockIdx.x * 256 + t;
    int v = (i < NN) ? g_cnt[i] : 0;
    sh[t] = v;
    __syncthreads();
    for (int o = 1; o < 256; o <<= 1) {
        int add = (t >= o) ? sh[t - o] : 0;
        __syncthreads();
        sh[t] += add;
        __syncthreads();
    }
    if (i < NN) {
        int rs = g_boff[blockIdx.x] + sh[t] - v;  // exclusive
        g_rowstart[i] = rs;
        g_cursor[i] = rs;
        if (i == NN - 1) g_rowstart[NN] = EE;
    }
}

__global__ void csr_fill_k(const int* __restrict__ ei) {
    int e = blockIdx.x * blockDim.x + threadIdx.x;
    if (e < EE) {
        int dst = ei[EE + e];
        int pos = atomicAdd(&g_cursor[dst], 1);
        g_csr[pos] = ei[e];
    }
}

// ---------------- GEMM: out = (X @ W) * dinv[row], FFMA2 packed ----------------
// Block tile: 64 rows x NC cols, 256 threads, per-thread 8 rows x (NC/32) cols.
// Accumulators pack adjacent column pairs into f32x2; per-column chain order
// is unchanged vs the scalar version -> bit-identical results.
template <int NC>
__device__ __forceinline__ void gemm_body(const float* __restrict__ X,
                                          const float* __restrict__ W,
                                          float* __restrict__ out) {
    constexpr int CPT = NC / 32;   // 4 or 2 cols per thread
    constexpr int CP2 = CPT / 2;   // 2 or 1 f32x2 pairs
    __shared__ __align__(16) float Xs[64 * 32];
    __shared__ __align__(16) float Ws[32 * NC];

    const int tid = threadIdx.x;
    const int tx = tid & 31;
    const int ty = tid >> 5;
    const int row0 = blockIdx.x * 64;

    unsigned long long acc[8][CP2];
#pragma unroll
    for (int i = 0; i < 8; i++)
#pragma unroll
        for (int j = 0; j < CP2; j++) acc[i][j] = 0ull;

    for (int kb = 0; kb < FF; kb += 32) {
#pragma unroll
        for (int i = 0; i < 8; i++) {
            int r = ty + i * 8;
            int gr = row0 + r;
            Xs[r * 32 + tx] = (gr < NN) ? X[(long)gr * FF + kb + tx] : 0.0f;
        }
#pragma unroll
        for (int i = 0; i < CPT; i++) {
            int idx = (tid + i * 256) * 4;
            int kk = idx / NC;
            int c = idx % NC;
            *(float4*)&Ws[kk * NC + c] = *(const float4*)&W[(long)(kb + kk) * NC + c];
        }
        __syncthreads();
#pragma unroll
        for (int kk = 0; kk < 32; kk++) {
            unsigned long long b2[CP2];
            if (CPT == 4) {
                float4 t = *(const float4*)&Ws[kk * NC + tx * 4];
                b2[0] = pk2(t.x, t.y);
                b2[CP2 - 1] = pk2(t.z, t.w);  // CP2==2; index trick keeps compiler happy
            } else {
                float2 t = *(const float2*)&Ws[kk * NC + tx * 2];
                b2[0] = pk2(t.x, t.y);
            }
#pragma unroll
            for (int i = 0; i < 8; i++) {
                float a = Xs[(ty * 8 + i) * 32 + kk];
                unsigned long long a2 = pk2(a, a);
#pragma unroll
                for (int j = 0; j < CP2; j++) fma2(acc[i][j], a2, b2[j]);
            }
        }
        __syncthreads();
    }
#pragma unroll
    for (int i = 0; i < 8; i++) {
        int gr = row0 + ty * 8 + i;
        if (gr < NN) {
            float s = g_dinv[gr];
#pragma unroll
            for (int j = 0; j < CP2; j++) {
                float2 v = unpk2(acc[i][j]);
                *(float2*)&out[(long)gr * NC + tx * CPT + 2 * j] =
                    make_float2(v.x * s, v.y * s);
            }
        }
    }
}

__global__ void gemm1_k(const float* __restrict__ x, const float* __restrict__ W1) {
    gemm_body<HH>(x, W1, g_hs1);
}
__global__ void gemm2_k(const float* __restrict__ W2) {
    gemm_body<ZZ>(g_h, W2, g_hs2);
}

// ---------------- gather: one warp per dst node, register accumulation ----------------
__global__ void gather1_k(const float* __restrict__ b1) {
    int gt = blockIdx.x * blockDim.x + threadIdx.x;
    int n = gt >> 5;
    int lane = gt & 31;
    if (n >= NN) return;
    int s = g_rowstart[n];
    int e = g_rowstart[n + 1];

    float4 acc = *(const float4*)&g_hs1[(long)n * 128 + lane * 4];  // self-loop

    for (int base = s; base < e; base += 32) {
        int idx = base + lane;
        int myi = (idx < e) ? g_csr[idx] : 0;
        int cnt = min(32, e - base);
        int j = 0;
        for (; j + 8 <= cnt; j += 8) {
            int ss[8];
#pragma unroll
            for (int q = 0; q < 8; q++) ss[q] = __shfl_sync(0xffffffffu, myi, j + q);
            float4 vv[8];
#pragma unroll
            for (int q = 0; q < 8; q++)
                vv[q] = *(const float4*)&g_hs1[(long)ss[q] * 128 + lane * 4];
#pragma unroll
            for (int q = 0; q < 8; q++) {
                acc.x += vv[q].x;
                acc.y += vv[q].y;
                acc.z += vv[q].z;
                acc.w += vv[q].w;
            }
        }
        for (; j < cnt; j++) {
            int s0 = __shfl_sync(0xffffffffu, myi, j);
            float4 v = *(const float4*)&g_hs1[(long)s0 * 128 + lane * 4];
            acc.x += v.x; acc.y += v.y; acc.z += v.z; acc.w += v.w;
        }
    }
    float d = g_dinv[n];
    float4 bb = *(const float4*)&b1[lane * 4];
    float4 o;
    o.x = fmaxf(fmaf(d, acc.x, bb.x), 0.0f);
    o.y = fmaxf(fmaf(d, acc.y, bb.y), 0.0f);
    o.z = fmaxf(fmaf(d, acc.z, bb.z), 0.0f);
    o.w = fmaxf(fmaf(d, acc.w, bb.w), 0.0f);
    *(float4*)&g_h[(long)n * 128 + lane * 4] = o;
}

__global__ void gather2_k(const float* __restrict__ b2) {
    int gt = blockIdx.x * blockDim.x + threadIdx.x;
    int n = gt >> 5;
    int lane = gt & 31;
    if (n >= NN) return;
    int s = g_rowstart[n];
    int e = g_rowstart[n + 1];

    float2 acc = *(const float2*)&g_hs2[(long)n * 64 + lane * 2];  // self-loop

    for (int base = s; base < e; base += 32) {
        int idx = base + lane;
        int myi = (idx < e) ? g_csr[idx] : 0;
        int cnt = min(32, e - base);
        int j = 0;
        for (; j + 8 <= cnt; j += 8) {
            int ss[8];
#pragma unroll
            for (int q = 0; q < 8; q++) ss[q] = __shfl_sync(0xffffffffu, myi, j + q);
            float2 vv[8];
#pragma unroll
            for (int q = 0; q < 8; q++)
                vv[q] = *(const float2*)&g_hs2[(long)ss[q] * 64 + lane * 2];
#pragma unroll
            for (int q = 0; q < 8; q++) {
                acc.x += vv[q].x;
                acc.y += vv[q].y;
            }
        }
        for (; j < cnt; j++) {
            int s0 = __shfl_sync(0xffffffffu, myi, j);
            float2 v = *(const float2*)&g_hs2[(long)s0 * 64 + lane * 2];
            acc.x += v.x; acc.y += v.y;
        }
    }
    float d = g_dinv[n];
    float2 bb = *(const float2*)&b2[lane * 2];
    float2 o;
    o.x = fmaf(d, acc.x, bb.x);
    o.y = fmaf(d, acc.y, bb.y);
    *(float2*)&g_lat[(long)n * 64 + lane * 2] = o;
}

// ---------------- decoder: one warp per edge pair ----------------
__global__ void decode_k(const int* __restrict__ pe,
                         const int* __restrict__ ne,
                         float* __restrict__ out) {
    int gt = blockIdx.x * blockDim.x + threadIdx.x;
    int w = gt >> 5;
    int lane = gt & 31;
    if (w >= 2 * EPOS) return;
    int a, b;
    if (w < EPOS) {
        a = pe[w];
        b = pe[EPOS + w];
    } else {
        int k = w - EPOS;
        a = ne[k];
        b = ne[EPOS + k];
    }
    float2 u = *(const float2*)&g_lat[(long)a * 64 + lane * 2];
    float2 v = *(const float2*)&g_lat[(long)b * 64 + lane * 2];
    float s = u.x * v.x + u.y * v.y;
#pragma unroll
    for (int o = 16; o > 0; o >>= 1) s += __shfl_xor_sync(0xffffffffu, s, o);
    if (lane == 0) out[w] = s;
}

// ---------------- launch (single stream) ----------------
extern "C" void kernel_launch(void* const* d_in, const int* in_sizes, int n_in,
                              void* d_out, int out_size) {
    const float* x = (const float*)d_in[0];
    const float* W1 = (const float*)d_in[1];
    const float* b1 = (const float*)d_in[2];
    const float* W2 = (const float*)d_in[3];
    const float* b2 = (const float*)d_in[4];
    const int* ei = (const int*)d_in[5];
    const int* pe = (const int*)d_in[6];
    const int* ne = (const int*)d_in[7];
    float* out = (float*)d_out;

    // CSR build + dinv
    cnt_init_k<<<(NN + 255) / 256, 256>>>();
    cnt_count_k<<<(EE + 255) / 256, 256>>>(ei);
    dinv_k<<<(NN + 255) / 256, 256>>>();
    scan_bsum_k<<<NCHUNK, 256>>>();
    scan_boff_k<<<1, 512>>>();
    scan_final_k<<<NCHUNK, 256>>>();
    csr_fill_k<<<(EE + 255) / 256, 256>>>(ei);

    // layer 1
    gemm1_k<<<(NN + 63) / 64, 256>>>(x, W1);
    gather1_k<<<(NN * 32 + 255) / 256, 256>>>(b1);

    // layer 2
    gemm2_k<<<(NN + 63) / 64, 256>>>(W2);
    gather2_k<<<(NN * 32 + 255) / 256, 256>>>(b2);

    decode_k<<<(2 * EPOS * 32 + 255) / 256, 256>>>(pe, ne, out);
}

// round 11
// speedup vs baseline: 1.0840x; 1.0452x over previous
#include <cuda_runtime.h>

#define NN 100000
#define FF 128
#define HH 128
#define ZZ 64
#define EE 1600000
#define EPOS 200000
#define NCHUNK ((NN + 255) / 256)   // 391

// ---- scratch (static device globals) ----
__device__ __align__(16) int   g_cnt[NN];          // dst histogram (no self-loop)
__device__ __align__(16) int   g_bsum[512];
__device__ __align__(16) int   g_boff[512];
__device__ __align__(16) int   g_rowstart[NN + 1];
__device__ __align__(16) int   g_cursor[NN];
__device__ __align__(16) int   g_csr[EE];          // src ids sorted by dst
__device__ __align__(16) float g_dinv[NN];
__device__ __align__(16) float g_hs1[NN * HH];     // (x@W1)*dinv[row]
__device__ __align__(16) float g_h[NN * HH];       // relu output
__device__ __align__(16) float g_hs2[NN * ZZ];     // (h@W2)*dinv[row]
__device__ __align__(16) float g_lat[NN * ZZ];     // latent

// ---- packed f32x2 helpers (sm_103a FFMA2) ----
__device__ __forceinline__ unsigned long long pk2(float x, float y) {
    unsigned long long r;
    asm("mov.b64 %0, {%1, %2};" : "=l"(r) : "f"(x), "f"(y));
    return r;
}
__device__ __forceinline__ void fma2(unsigned long long& d,
                                     unsigned long long a,
                                     unsigned long long b) {
    asm("fma.rn.f32x2 %0, %1, %2, %0;" : "+l"(d) : "l"(a), "l"(b));
}
__device__ __forceinline__ float2 unpk2(unsigned long long v) {
    float x, y;
    asm("mov.b64 {%0, %1}, %2;" : "=f"(x), "=f"(y) : "l"(v));
    return make_float2(x, y);
}

// ---------------- histogram / dinv ----------------
__global__ void cnt_init_k() {
    int i = blockIdx.x * blockDim.x + threadIdx.x;
    if (i < NN) g_cnt[i] = 0;
}

__global__ void cnt_count_k(const int* __restrict__ ei) {
    int e = blockIdx.x * blockDim.x + threadIdx.x;
    if (e < EE) atomicAdd(&g_cnt[ei[EE + e]], 1);
}

__global__ void dinv_k() {
    int i = blockIdx.x * blockDim.x + threadIdx.x;
    if (i < NN) g_dinv[i] = rsqrtf((float)(g_cnt[i] + 1));  // +1 self-loop
}

// ---------------- scan (3 small kernels) ----------------
__global__ void scan_bsum_k() {
    __shared__ int sh[256];
    int i = blockIdx.x * 256 + threadIdx.x;
    sh[threadIdx.x] = (i < NN) ? g_cnt[i] : 0;
    __syncthreads();
    for (int o = 128; o > 0; o >>= 1) {
        if (threadIdx.x < o) sh[threadIdx.x] += sh[threadIdx.x + o];
        __syncthreads();
    }
    if (threadIdx.x == 0) g_bsum[blockIdx.x] = sh[0];
}

__global__ void scan_boff_k() {  // 1 block, 512 threads; exclusive scan of g_bsum
    __shared__ int sh[512];
    int t = threadIdx.x;
    int v = (t < NCHUNK) ? g_bsum[t] : 0;
    sh[t] = v;
    __syncthreads();
    for (int o = 1; o < 512; o <<= 1) {
        int add = (t >= o) ? sh[t - o] : 0;
        __syncthreads();
        sh[t] += add;
        __syncthreads();
    }
    g_boff[t] = sh[t] - v;  // exclusive
}

__global__ void scan_final_k() {
    __shared__ int sh[256];
    int t = threadIdx.x;
    int i = blockIdx.x * 256 + t;
    int v = (i < NN) ? g_cnt[i] : 0;
    sh[t] = v;
    __syncthreads();
    for (int o = 1; o < 256; o <<= 1) {
        int add = (t >= o) ? sh[t - o] : 0;
        __syncthreads();
        sh[t] += add;
        __syncthreads();
    }
    if (i < NN) {
        int rs = g_boff[blockIdx.x] + sh[t] - v;  // exclusive
        g_rowstart[i] = rs;
        g_cursor[i] = rs;
        if (i == NN - 1) g_rowstart[NN] = EE;
    }
}

__global__ void csr_fill_k(const int* __restrict__ ei) {
    int e = blockIdx.x * blockDim.x + threadIdx.x;
    if (e < EE) {
        int dst = ei[EE + e];
        int pos = atomicAdd(&g_cursor[dst], 1);
        g_csr[pos] = ei[e];
    }
}

// ---------------- GEMM: out = (X @ W) * dinv[row], FFMA2 packed ----------------
template <int NC>
__device__ __forceinline__ void gemm_body(const float* __restrict__ X,
                                          const float* __restrict__ W,
                                          float* __restrict__ out) {
    constexpr int CPT = NC / 32;   // 4 or 2 cols per thread
    constexpr int CP2 = CPT / 2;   // 2 or 1 f32x2 pairs
    __shared__ __align__(16) float Xs[64 * 32];
    __shared__ __align__(16) float Ws[32 * NC];

    const int tid = threadIdx.x;
    const int tx = tid & 31;
    const int ty = tid >> 5;
    const int row0 = blockIdx.x * 64;

    unsigned long long acc[8][CP2];
#pragma unroll
    for (int i = 0; i < 8; i++)
#pragma unroll
        for (int j = 0; j < CP2; j++) acc[i][j] = 0ull;

    for (int kb = 0; kb < FF; kb += 32) {
#pragma unroll
        for (int i = 0; i < 8; i++) {
            int r = ty + i * 8;
            int gr = row0 + r;
            Xs[r * 32 + tx] = (gr < NN) ? X[(long)gr * FF + kb + tx] : 0.0f;
        }
#pragma unroll
        for (int i = 0; i < CPT; i++) {
            int idx = (tid + i * 256) * 4;
            int kk = idx / NC;
            int c = idx % NC;
            *(float4*)&Ws[kk * NC + c] = *(const float4*)&W[(long)(kb + kk) * NC + c];
        }
        __syncthreads();
#pragma unroll
        for (int kk = 0; kk < 32; kk++) {
            unsigned long long b2[CP2];
            if (CPT == 4) {
                float4 t = *(const float4*)&Ws[kk * NC + tx * 4];
                b2[0] = pk2(t.x, t.y);
                b2[CP2 - 1] = pk2(t.z, t.w);
            } else {
                float2 t = *(const float2*)&Ws[kk * NC + tx * 2];
                b2[0] = pk2(t.x, t.y);
            }
#pragma unroll
            for (int i = 0; i < 8; i++) {
                float a = Xs[(ty * 8 + i) * 32 + kk];
                unsigned long long a2 = pk2(a, a);
#pragma unroll
                for (int j = 0; j < CP2; j++) fma2(acc[i][j], a2, b2[j]);
            }
        }
        __syncthreads();
    }
#pragma unroll
    for (int i = 0; i < 8; i++) {
        int gr = row0 + ty * 8 + i;
        if (gr < NN) {
            float s = g_dinv[gr];
#pragma unroll
            for (int j = 0; j < CP2; j++) {
                float2 v = unpk2(acc[i][j]);
                *(float2*)&out[(long)gr * NC + tx * CPT + 2 * j] =
                    make_float2(v.x * s, v.y * s);
            }
        }
    }
}

__global__ void gemm1_k(const float* __restrict__ x, const float* __restrict__ W1) {
    gemm_body<HH>(x, W1, g_hs1);
}
__global__ void gemm2_k(const float* __restrict__ W2) {
    gemm_body<ZZ>(g_h, W2, g_hs2);
}

// ---------------- gather: one warp per dst node, register accumulation ----------------
__global__ void gather1_k(const float* __restrict__ b1) {
    int gt = blockIdx.x * blockDim.x + threadIdx.x;
    int n = gt >> 5;
    int lane = gt & 31;
    if (n >= NN) return;
    int s = g_rowstart[n];
    int e = g_rowstart[n + 1];

    float4 acc = *(const float4*)&g_hs1[(long)n * 128 + lane * 4];  // self-loop

    for (int base = s; base < e; base += 32) {
        int idx = base + lane;
        int myi = (idx < e) ? g_csr[idx] : 0;
        int cnt = min(32, e - base);
        int j = 0;
        for (; j + 8 <= cnt; j += 8) {
            int ss[8];
#pragma unroll
            for (int q = 0; q < 8; q++) ss[q] = __shfl_sync(0xffffffffu, myi, j + q);
            float4 vv[8];
#pragma unroll
            for (int q = 0; q < 8; q++)
                vv[q] = *(const float4*)&g_hs1[(long)ss[q] * 128 + lane * 4];
#pragma unroll
            for (int q = 0; q < 8; q++) {
                acc.x += vv[q].x;
                acc.y += vv[q].y;
                acc.z += vv[q].z;
                acc.w += vv[q].w;
            }
        }
        for (; j < cnt; j++) {
            int s0 = __shfl_sync(0xffffffffu, myi, j);
            float4 v = *(const float4*)&g_hs1[(long)s0 * 128 + lane * 4];
            acc.x += v.x; acc.y += v.y; acc.z += v.z; acc.w += v.w;
        }
    }
    float d = g_dinv[n];
    float4 bb = *(const float4*)&b1[lane * 4];
    float4 o;
    o.x = fmaxf(fmaf(d, acc.x, bb.x), 0.0f);
    o.y = fmaxf(fmaf(d, acc.y, bb.y), 0.0f);
    o.z = fmaxf(fmaf(d, acc.z, bb.z), 0.0f);
    o.w = fmaxf(fmaf(d, acc.w, bb.w), 0.0f);
    *(float4*)&g_h[(long)n * 128 + lane * 4] = o;
}

__global__ void gather2_k(const float* __restrict__ b2) {
    int gt = blockIdx.x * blockDim.x + threadIdx.x;
    int n = gt >> 5;
    int lane = gt & 31;
    if (n >= NN) return;
    int s = g_rowstart[n];
    int e = g_rowstart[n + 1];

    float2 acc = *(const float2*)&g_hs2[(long)n * 64 + lane * 2];  // self-loop

    for (int base = s; base < e; base += 32) {
        int idx = base + lane;
        int myi = (idx < e) ? g_csr[idx] : 0;
        int cnt = min(32, e - base);
        int j = 0;
        for (; j + 8 <= cnt; j += 8) {
            int ss[8];
#pragma unroll
            for (int q = 0; q < 8; q++) ss[q] = __shfl_sync(0xffffffffu, myi, j + q);
            float2 vv[8];
#pragma unroll
            for (int q = 0; q < 8; q++)
                vv[q] = *(const float2*)&g_hs2[(long)ss[q] * 64 + lane * 2];
#pragma unroll
            for (int q = 0; q < 8; q++) {
                acc.x += vv[q].x;
                acc.y += vv[q].y;
            }
        }
        for (; j < cnt; j++) {
            int s0 = __shfl_sync(0xffffffffu, myi, j);
            float2 v = *(const float2*)&g_hs2[(long)s0 * 64 + lane * 2];
            acc.x += v.x; acc.y += v.y;
        }
    }
    float d = g_dinv[n];
    float2 bb = *(const float2*)&b2[lane * 2];
    float2 o;
    o.x = fmaf(d, acc.x, bb.x);
    o.y = fmaf(d, acc.y, bb.y);
    *(float2*)&g_lat[(long)n * 64 + lane * 2] = o;
}

// ---------------- decoder: one warp per edge pair ----------------
__global__ void decode_k(const int* __restrict__ pe,
                         const int* __restrict__ ne,
                         float* __restrict__ out) {
    int gt = blockIdx.x * blockDim.x + threadIdx.x;
    int w = gt >> 5;
    int lane = gt & 31;
    if (w >= 2 * EPOS) return;
    int a, b;
    if (w < EPOS) {
        a = pe[w];
        b = pe[EPOS + w];
    } else {
        int k = w - EPOS;
        a = ne[k];
        b = ne[EPOS + k];
    }
    float2 u = *(const float2*)&g_lat[(long)a * 64 + lane * 2];
    float2 v = *(const float2*)&g_lat[(long)b * 64 + lane * 2];
    float s = u.x * v.x + u.y * v.y;
#pragma unroll
    for (int o = 16; o > 0; o >>= 1) s += __shfl_xor_sync(0xffffffffu, s, o);
    if (lane == 0) out[w] = s;
}

// ---------------- launch: fork scan/fill chain concurrent with gemm1 ----------------
extern "C" void kernel_launch(void* const* d_in, const int* in_sizes, int n_in,
                              void* d_out, int out_size) {
    const float* x = (const float*)d_in[0];
    const float* W1 = (const float*)d_in[1];
    const float* b1 = (const float*)d_in[2];
    const float* W2 = (const float*)d_in[3];
    const float* b2 = (const float*)d_in[4];
    const int* ei = (const int*)d_in[5];
    const int* pe = (const int*)d_in[6];
    const int* ne = (const int*)d_in[7];
    float* out = (float*)d_out;

    static cudaStream_t sB = nullptr;
    static cudaEvent_t evF = nullptr, evJ = nullptr;
    if (sB == nullptr) {
        cudaStreamCreateWithFlags(&sB, cudaStreamNonBlocking);
        cudaEventCreateWithFlags(&evF, cudaEventDisableTiming);
        cudaEventCreateWithFlags(&evJ, cudaEventDisableTiming);
    }

    // degree histogram (needed by BOTH branches)
    cnt_init_k<<<(NN + 255) / 256, 256>>>();
    cnt_count_k<<<(EE + 255) / 256, 256>>>(ei);

    // fork: scan+fill on sB (needs only g_cnt); dinv+gemm1 on stream 0
    cudaEventRecord(evF, 0);
    cudaStreamWaitEvent(sB, evF, 0);
    scan_bsum_k<<<NCHUNK, 256, 0, sB>>>();
    scan_boff_k<<<1, 512, 0, sB>>>();
    scan_final_k<<<NCHUNK, 256, 0, sB>>>();
    csr_fill_k<<<(EE + 255) / 256, 256, 0, sB>>>(ei);
    cudaEventRecord(evJ, sB);

    dinv_k<<<(NN + 255) / 256, 256>>>();
    gemm1_k<<<(NN + 63) / 64, 256>>>(x, W1);

    // join: gather1 needs csr_fill + gemm1
    cudaStreamWaitEvent(0, evJ, 0);

    gather1_k<<<(NN * 32 + 255) / 256, 256>>>(b1);
    gemm2_k<<<(NN + 63) / 64, 256>>>(W2);
    gather2_k<<<(NN * 32 + 255) / 256, 256>>>(b2);
    decode_k<<<(2 * EPOS * 32 + 255) / 256, 256>>>(pe, ne, out);
}

// round 12
// speedup vs baseline: 1.1503x; 1.0612x over previous
#include <cuda_runtime.h>
#include <cuda_fp16.h>

#define NN 100000
#define FF 128
#define HH 128
#define ZZ 64
#define EE 1600000
#define EPOS 200000
#define NCHUNK ((NN + 255) / 256)   // 391

// ---- scratch (static device globals) ----
__device__ __align__(16) int      g_cnt[NN];
__device__ __align__(16) int      g_bsum[512];
__device__ __align__(16) int      g_boff[512];
__device__ __align__(16) int      g_rowstart[NN + 1];
__device__ __align__(16) int      g_cursor[NN];
__device__ __align__(16) int      g_csr[EE];
__device__ __align__(16) float    g_dinv[NN];
__device__ __align__(16) unsigned g_hs1h[NN * 64];   // (x@W1)*dinv as half2 pairs (128 cols)
__device__ __align__(16) float    g_h[NN * HH];      // relu output (fp32)
__device__ __align__(16) float    g_hs2[NN * ZZ];    // (h@W2)*dinv (fp32)
__device__ __align__(16) float    g_lat[NN * ZZ];    // latent

// ---- packed f32x2 helpers (sm_103a FFMA2) ----
__device__ __forceinline__ unsigned long long pk2(float x, float y) {
    unsigned long long r;
    asm("mov.b64 %0, {%1, %2};" : "=l"(r) : "f"(x), "f"(y));
    return r;
}
__device__ __forceinline__ void fma2(unsigned long long& d,
                                     unsigned long long a,
                                     unsigned long long b) {
    asm("fma.rn.f32x2 %0, %1, %2, %0;" : "+l"(d) : "l"(a), "l"(b));
}
__device__ __forceinline__ float2 unpk2(unsigned long long v) {
    float x, y;
    asm("mov.b64 {%0, %1}, %2;" : "=f"(x), "=f"(y) : "l"(v));
    return make_float2(x, y);
}

// ---------------- histogram / dinv ----------------
__global__ void cnt_init_k() {
    int i = blockIdx.x * blockDim.x + threadIdx.x;
    if (i < NN) g_cnt[i] = 0;
}

__global__ void cnt_count_k(const int* __restrict__ ei) {
    int e = blockIdx.x * blockDim.x + threadIdx.x;
    if (e < EE) atomicAdd(&g_cnt[ei[EE + e]], 1);
}

__global__ void dinv_k() {
    int i = blockIdx.x * blockDim.x + threadIdx.x;
    if (i < NN) g_dinv[i] = rsqrtf((float)(g_cnt[i] + 1));
}

// ---------------- scan (3 small kernels) ----------------
__global__ void scan_bsum_k() {
    __shared__ int sh[256];
    int i = blockIdx.x * 256 + threadIdx.x;
    sh[threadIdx.x] = (i < NN) ? g_cnt[i] : 0;
    __syncthreads();
    for (int o = 128; o > 0; o >>= 1) {
        if (threadIdx.x < o) sh[threadIdx.x] += sh[threadIdx.x + o];
        __syncthreads();
    }
    if (threadIdx.x == 0) g_bsum[blockIdx.x] = sh[0];
}

__global__ void scan_boff_k() {
    __shared__ int sh[512];
    int t = threadIdx.x;
    int v = (t < NCHUNK) ? g_bsum[t] : 0;
    sh[t] = v;
    __syncthreads();
    for (int o = 1; o < 512; o <<= 1) {
        int add = (t >= o) ? sh[t - o] : 0;
        __syncthreads();
        sh[t] += add;
        __syncthreads();
    }
    g_boff[t] = sh[t] - v;
}

__global__ void scan_final_k() {
    __shared__ int sh[256];
    int t = threadIdx.x;
    int i = blockIdx.x * 256 + t;
    int v = (i < NN) ? g_cnt[i] : 0;
    sh[t] = v;
    __syncthreads();
    for (int o = 1; o < 256; o <<= 1) {
        int add = (t >= o) ? sh[t - o] : 0;
        __syncthreads();
        sh[t] += add;
        __syncthreads();
    }
    if (i < NN) {
        int rs = g_boff[blockIdx.x] + sh[t] - v;
        g_rowstart[i] = rs;
        g_cursor[i] = rs;
        if (i == NN - 1) g_rowstart[NN] = EE;
    }
}

__global__ void csr_fill_k(const int* __restrict__ ei) {
    int e = blockIdx.x * blockDim.x + threadIdx.x;
    if (e < EE) {
        int dst = ei[EE + e];
        int pos = atomicAdd(&g_cursor[dst], 1);
        g_csr[pos] = ei[e];
    }
}

// ---------------- GEMM: out = (X @ W) * dinv[row], FFMA2 packed ----------------
// HOUT=true: store half2 pairs to outh (NC=128 only). HOUT=false: fp32 to outf.
template <int NC, bool HOUT>
__device__ __forceinline__ void gemm_body(const float* __restrict__ X,
                                          const float* __restrict__ W,
                                          float* __restrict__ outf,
                                          unsigned* __restrict__ outh) {
    constexpr int CPT = NC / 32;
    constexpr int CP2 = CPT / 2;
    __shared__ __align__(16) float Xs[64 * 32];
    __shared__ __align__(16) float Ws[32 * NC];

    const int tid = threadIdx.x;
    const int tx = tid & 31;
    const int ty = tid >> 5;
    const int row0 = blockIdx.x * 64;

    unsigned long long acc[8][CP2];
#pragma unroll
    for (int i = 0; i < 8; i++)
#pragma unroll
        for (int j = 0; j < CP2; j++) acc[i][j] = 0ull;

    for (int kb = 0; kb < FF; kb += 32) {
#pragma unroll
        for (int i = 0; i < 8; i++) {
            int r = ty + i * 8;
            int gr = row0 + r;
            Xs[r * 32 + tx] = (gr < NN) ? X[(long)gr * FF + kb + tx] : 0.0f;
        }
#pragma unroll
        for (int i = 0; i < CPT; i++) {
            int idx = (tid + i * 256) * 4;
            int kk = idx / NC;
            int c = idx % NC;
            *(float4*)&Ws[kk * NC + c] = *(const float4*)&W[(long)(kb + kk) * NC + c];
        }
        __syncthreads();
#pragma unroll
        for (int kk = 0; kk < 32; kk++) {
            unsigned long long b2[CP2];
            if (CPT == 4) {
                float4 t = *(const float4*)&Ws[kk * NC + tx * 4];
                b2[0] = pk2(t.x, t.y);
                b2[CP2 - 1] = pk2(t.z, t.w);
            } else {
                float2 t = *(const float2*)&Ws[kk * NC + tx * 2];
                b2[0] = pk2(t.x, t.y);
            }
#pragma unroll
            for (int i = 0; i < 8; i++) {
                float a = Xs[(ty * 8 + i) * 32 + kk];
                unsigned long long a2 = pk2(a, a);
#pragma unroll
                for (int j = 0; j < CP2; j++) fma2(acc[i][j], a2, b2[j]);
            }
        }
        __syncthreads();
    }
#pragma unroll
    for (int i = 0; i < 8; i++) {
        int gr = row0 + ty * 8 + i;
        if (gr < NN) {
            float s = g_dinv[gr];
#pragma unroll
            for (int j = 0; j < CP2; j++) {
                float2 v = unpk2(acc[i][j]);
                if (HOUT) {
                    __half2 hv = __float22half2_rn(make_float2(v.x * s, v.y * s));
                    outh[(long)gr * 64 + tx * 2 + j] = *(unsigned*)&hv;
                } else {
                    *(float2*)&outf[(long)gr * NC + tx * CPT + 2 * j] =
                        make_float2(v.x * s, v.y * s);
                }
            }
        }
    }
}

__global__ void gemm1_k(const float* __restrict__ x, const float* __restrict__ W1) {
    gemm_body<HH, true>(x, W1, nullptr, g_hs1h);
}
__global__ void gemm2_k(const float* __restrict__ W2) {
    gemm_body<ZZ, false>(g_h, W2, g_hs2, nullptr);
}

// ---------------- gather1: fp16 rows, fp32 accumulation ----------------
__device__ __forceinline__ void h2acc(float4& acc, uint2 v) {
    float2 lo = __half22float2(*(__half2*)&v.x);
    float2 hi = __half22float2(*(__half2*)&v.y);
    acc.x += lo.x; acc.y += lo.y; acc.z += hi.x; acc.w += hi.y;
}

__global__ void gather1_k(const float* __restrict__ b1) {
    int gt = blockIdx.x * blockDim.x + threadIdx.x;
    int n = gt >> 5;
    int lane = gt & 31;
    if (n >= NN) return;
    int s = g_rowstart[n];
    int e = g_rowstart[n + 1];

    float4 acc = make_float4(0.f, 0.f, 0.f, 0.f);
    h2acc(acc, *(const uint2*)&g_hs1h[(long)n * 64 + lane * 2]);  // self-loop

    for (int base = s; base < e; base += 32) {
        int idx = base + lane;
        int myi = (idx < e) ? g_csr[idx] : 0;
        int cnt = min(32, e - base);
        int j = 0;
        for (; j + 8 <= cnt; j += 8) {
            int ss[8];
#pragma unroll
            for (int q = 0; q < 8; q++) ss[q] = __shfl_sync(0xffffffffu, myi, j + q);
            uint2 vv[8];
#pragma unroll
            for (int q = 0; q < 8; q++)
                vv[q] = *(const uint2*)&g_hs1h[(long)ss[q] * 64 + lane * 2];
#pragma unroll
            for (int q = 0; q < 8; q++) h2acc(acc, vv[q]);
        }
        for (; j < cnt; j++) {
            int s0 = __shfl_sync(0xffffffffu, myi, j);
            h2acc(acc, *(const uint2*)&g_hs1h[(long)s0 * 64 + lane * 2]);
        }
    }
    float d = g_dinv[n];
    float4 bb = *(const float4*)&b1[lane * 4];
    float4 o;
    o.x = fmaxf(fmaf(d, acc.x, bb.x), 0.0f);
    o.y = fmaxf(fmaf(d, acc.y, bb.y), 0.0f);
    o.z = fmaxf(fmaf(d, acc.z, bb.z), 0.0f);
    o.w = fmaxf(fmaf(d, acc.w, bb.w), 0.0f);
    *(float4*)&g_h[(long)n * 128 + lane * 4] = o;
}

// ---------------- gather2: fp32 (unchanged) ----------------
__global__ void gather2_k(const float* __restrict__ b2) {
    int gt = blockIdx.x * blockDim.x + threadIdx.x;
    int n = gt >> 5;
    int lane = gt & 31;
    if (n >= NN) return;
    int s = g_rowstart[n];
    int e = g_rowstart[n + 1];

    float2 acc = *(const float2*)&g_hs2[(long)n * 64 + lane * 2];  // self-loop

    for (int base = s; base < e; base += 32) {
        int idx = base + lane;
        int myi = (idx < e) ? g_csr[idx] : 0;
        int cnt = min(32, e - base);
        int j = 0;
        for (; j + 8 <= cnt; j += 8) {
            int ss[8];
#pragma unroll
            for (int q = 0; q < 8; q++) ss[q] = __shfl_sync(0xffffffffu, myi, j + q);
            float2 vv[8];
#pragma unroll
            for (int q = 0; q < 8; q++)
                vv[q] = *(const float2*)&g_hs2[(long)ss[q] * 64 + lane * 2];
#pragma unroll
            for (int q = 0; q < 8; q++) {
                acc.x += vv[q].x;
                acc.y += vv[q].y;
            }
        }
        for (; j < cnt; j++) {
            int s0 = __shfl_sync(0xffffffffu, myi, j);
            float2 v = *(const float2*)&g_hs2[(long)s0 * 64 + lane * 2];
            acc.x += v.x; acc.y += v.y;
        }
    }
    float d = g_dinv[n];
    float2 bb = *(const float2*)&b2[lane * 2];
    float2 o;
    o.x = fmaf(d, acc.x, bb.x);
    o.y = fmaf(d, acc.y, bb.y);
    *(float2*)&g_lat[(long)n * 64 + lane * 2] = o;
}

// ---------------- decoder ----------------
__global__ void decode_k(const int* __restrict__ pe,
                         const int* __restrict__ ne,
                         float* __restrict__ out) {
    int gt = blockIdx.x * blockDim.x + threadIdx.x;
    int w = gt >> 5;
    int lane = gt & 31;
    if (w >= 2 * EPOS) return;
    int a, b;
    if (w < EPOS) {
        a = pe[w];
        b = pe[EPOS + w];
    } else {
        int k = w - EPOS;
        a = ne[k];
        b = ne[EPOS + k];
    }
    float2 u = *(const float2*)&g_lat[(long)a * 64 + lane * 2];
    float2 v = *(const float2*)&g_lat[(long)b * 64 + lane * 2];
    float s = u.x * v.x + u.y * v.y;
#pragma unroll
    for (int o = 16; o > 0; o >>= 1) s += __shfl_xor_sync(0xffffffffu, s, o);
    if (lane == 0) out[w] = s;
}

// ---------------- launch: fork scan/fill chain concurrent with gemm1 ----------------
extern "C" void kernel_launch(void* const* d_in, const int* in_sizes, int n_in,
                              void* d_out, int out_size) {
    const float* x = (const float*)d_in[0];
    const float* W1 = (const float*)d_in[1];
    const float* b1 = (const float*)d_in[2];
    const float* W2 = (const float*)d_in[3];
    const float* b2 = (const float*)d_in[4];
    const int* ei = (const int*)d_in[5];
    const int* pe = (const int*)d_in[6];
    const int* ne = (const int*)d_in[7];
    float* out = (float*)d_out;

    static cudaStream_t sB = nullptr;
    static cudaEvent_t evF = nullptr, evJ = nullptr;
    if (sB == nullptr) {
        cudaStreamCreateWithFlags(&sB, cudaStreamNonBlocking);
        cudaEventCreateWithFlags(&evF, cudaEventDisableTiming);
        cudaEventCreateWithFlags(&evJ, cudaEventDisableTiming);
    }

    // degree histogram (needed by BOTH branches)
    cnt_init_k<<<(NN + 255) / 256, 256>>>();
    cnt_count_k<<<(EE + 255) / 256, 256>>>(ei);

    // fork: scan+fill on sB (needs only g_cnt); dinv+gemm1 on stream 0
    cudaEventRecord(evF, 0);
    cudaStreamWaitEvent(sB, evF, 0);
    scan_bsum_k<<<NCHUNK, 256, 0, sB>>>();
    scan_boff_k<<<1, 512, 0, sB>>>();
    scan_final_k<<<NCHUNK, 256, 0, sB>>>();
    csr_fill_k<<<(EE + 255) / 256, 256, 0, sB>>>(ei);
    cudaEventRecord(evJ, sB);

    dinv_k<<<(NN + 255) / 256, 256>>>();
    gemm1_k<<<(NN + 63) / 64, 256>>>(x, W1);

    // join: gather1 needs csr_fill + gemm1
    cudaStreamWaitEvent(0, evJ, 0);

    gather1_k<<<(NN * 32 + 255) / 256, 256>>>(b1);
    gemm2_k<<<(NN + 63) / 64, 256>>>(W2);
    gather2_k<<<(NN * 32 + 255) / 256, 256>>>(b2);
    decode_k<<<(2 * EPOS * 32 + 255) / 256, 256>>>(pe, ne, out);
}

// round 13
// speedup vs baseline: 1.1946x; 1.0385x over previous
#include <cuda_runtime.h>
#include <cuda_fp16.h>

#define NN 100000
#define FF 128
#define HH 128
#define ZZ 64
#define EE 1600000
#define EPOS 200000
#define NCHUNK ((NN + 255) / 256)   // 391

// ---- scratch (static device globals) ----
__device__ __align__(16) int      g_cnt[NN];
__device__ __align__(16) int      g_bsum[512];
__device__ __align__(16) int      g_boff[512];
__device__ __align__(16) int      g_rowstart[NN + 1];
__device__ __align__(16) int      g_cursor[NN];
__device__ __align__(16) int      g_csr[EE];
__device__ __align__(16) float    g_dinv[NN];
__device__ __align__(16) unsigned g_hs1h[NN * 64];   // (x@W1)*dinv as half2 (128 cols)
__device__ __align__(16) float    g_h[NN * HH];      // relu output (fp32, gemm2 input)
__device__ __align__(16) unsigned g_hs2h[NN * 32];   // (h@W2)*dinv as half2 (64 cols)
__device__ __align__(16) unsigned g_lath[NN * 32];   // latent as half2 (64 cols)

// ---- packed f32x2 helpers (sm_103a FFMA2) ----
__device__ __forceinline__ unsigned long long pk2(float x, float y) {
    unsigned long long r;
    asm("mov.b64 %0, {%1, %2};" : "=l"(r) : "f"(x), "f"(y));
    return r;
}
__device__ __forceinline__ void fma2(unsigned long long& d,
                                     unsigned long long a,
                                     unsigned long long b) {
    asm("fma.rn.f32x2 %0, %1, %2, %0;" : "+l"(d) : "l"(a), "l"(b));
}
__device__ __forceinline__ float2 unpk2(unsigned long long v) {
    float x, y;
    asm("mov.b64 {%0, %1}, %2;" : "=f"(x), "=f"(y) : "l"(v));
    return make_float2(x, y);
}

// ---------------- histogram / dinv ----------------
__global__ void cnt_init_k() {
    int i = blockIdx.x * blockDim.x + threadIdx.x;
    if (i < NN) g_cnt[i] = 0;
}

__global__ void cnt_count_k(const int* __restrict__ ei) {
    int e = blockIdx.x * blockDim.x + threadIdx.x;
    if (e < EE) atomicAdd(&g_cnt[ei[EE + e]], 1);
}

__global__ void dinv_k() {
    int i = blockIdx.x * blockDim.x + threadIdx.x;
    if (i < NN) g_dinv[i] = rsqrtf((float)(g_cnt[i] + 1));
}

// ---------------- scan (3 small kernels) ----------------
__global__ void scan_bsum_k() {
    __shared__ int sh[256];
    int i = blockIdx.x * 256 + threadIdx.x;
    sh[threadIdx.x] = (i < NN) ? g_cnt[i] : 0;
    __syncthreads();
    for (int o = 128; o > 0; o >>= 1) {
        if (threadIdx.x < o) sh[threadIdx.x] += sh[threadIdx.x + o];
        __syncthreads();
    }
    if (threadIdx.x == 0) g_bsum[blockIdx.x] = sh[0];
}

__global__ void scan_boff_k() {
    __shared__ int sh[512];
    int t = threadIdx.x;
    int v = (t < NCHUNK) ? g_bsum[t] : 0;
    sh[t] = v;
    __syncthreads();
    for (int o = 1; o < 512; o <<= 1) {
        int add = (t >= o) ? sh[t - o] : 0;
        __syncthreads();
        sh[t] += add;
        __syncthreads();
    }
    g_boff[t] = sh[t] - v;
}

__global__ void scan_final_k() {
    __shared__ int sh[256];
    int t = threadIdx.x;
    int i = blockIdx.x * 256 + t;
    int v = (i < NN) ? g_cnt[i] : 0;
    sh[t] = v;
    __syncthreads();
    for (int o = 1; o < 256; o <<= 1) {
        int add = (t >= o) ? sh[t - o] : 0;
        __syncthreads();
        sh[t] += add;
        __syncthreads();
    }
    if (i < NN) {
        int rs = g_boff[blockIdx.x] + sh[t] - v;
        g_rowstart[i] = rs;
        g_cursor[i] = rs;
        if (i == NN - 1) g_rowstart[NN] = EE;
    }
}

__global__ void csr_fill_k(const int* __restrict__ ei) {
    int e = blockIdx.x * blockDim.x + threadIdx.x;
    if (e < EE) {
        int dst = ei[EE + e];
        int pos = atomicAdd(&g_cursor[dst], 1);
        g_csr[pos] = ei[e];
    }
}

// ---------------- GEMM: out = (X @ W) * dinv[row], FFMA2, half2 output ----------------
template <int NC>
__device__ __forceinline__ void gemm_body(const float* __restrict__ X,
                                          const float* __restrict__ W,
                                          unsigned* __restrict__ outh) {
    constexpr int CPT = NC / 32;
    constexpr int CP2 = CPT / 2;
    __shared__ __align__(16) float Xs[64 * 32];
    __shared__ __align__(16) float Ws[32 * NC];

    const int tid = threadIdx.x;
    const int tx = tid & 31;
    const int ty = tid >> 5;
    const int row0 = blockIdx.x * 64;

    unsigned long long acc[8][CP2];
#pragma unroll
    for (int i = 0; i < 8; i++)
#pragma unroll
        for (int j = 0; j < CP2; j++) acc[i][j] = 0ull;

    for (int kb = 0; kb < FF; kb += 32) {
#pragma unroll
        for (int i = 0; i < 8; i++) {
            int r = ty + i * 8;
            int gr = row0 + r;
            Xs[r * 32 + tx] = (gr < NN) ? X[(long)gr * FF + kb + tx] : 0.0f;
        }
#pragma unroll
        for (int i = 0; i < CPT; i++) {
            int idx = (tid + i * 256) * 4;
            int kk = idx / NC;
            int c = idx % NC;
            *(float4*)&Ws[kk * NC + c] = *(const float4*)&W[(long)(kb + kk) * NC + c];
        }
        __syncthreads();
#pragma unroll
        for (int kk = 0; kk < 32; kk++) {
            unsigned long long b2[CP2];
            if (CPT == 4) {
                float4 t = *(const float4*)&Ws[kk * NC + tx * 4];
                b2[0] = pk2(t.x, t.y);
                b2[CP2 - 1] = pk2(t.z, t.w);
            } else {
                float2 t = *(const float2*)&Ws[kk * NC + tx * 2];
                b2[0] = pk2(t.x, t.y);
            }
#pragma unroll
            for (int i = 0; i < 8; i++) {
                float a = Xs[(ty * 8 + i) * 32 + kk];
                unsigned long long a2 = pk2(a, a);
#pragma unroll
                for (int j = 0; j < CP2; j++) fma2(acc[i][j], a2, b2[j]);
            }
        }
        __syncthreads();
    }
#pragma unroll
    for (int i = 0; i < 8; i++) {
        int gr = row0 + ty * 8 + i;
        if (gr < NN) {
            float s = g_dinv[gr];
#pragma unroll
            for (int j = 0; j < CP2; j++) {
                float2 v = unpk2(acc[i][j]);
                __half2 hv = __float22half2_rn(make_float2(v.x * s, v.y * s));
                outh[(long)gr * (NC / 2) + tx * CP2 + j] = *(unsigned*)&hv;
            }
        }
    }
}

__global__ void gemm1_k(const float* __restrict__ x, const float* __restrict__ W1) {
    gemm_body<HH>(x, W1, g_hs1h);
}
__global__ void gemm2_k(const float* __restrict__ W2) {
    gemm_body<ZZ>(g_h, W2, g_hs2h);
}

// ---------------- gather1: fp16 rows (128 cols), fp32 accumulation ----------------
__device__ __forceinline__ void h2acc4(float4& acc, uint2 v) {
    float2 lo = __half22float2(*(__half2*)&v.x);
    float2 hi = __half22float2(*(__half2*)&v.y);
    acc.x += lo.x; acc.y += lo.y; acc.z += hi.x; acc.w += hi.y;
}

__global__ void gather1_k(const float* __restrict__ b1) {
    int gt = blockIdx.x * blockDim.x + threadIdx.x;
    int n = gt >> 5;
    int lane = gt & 31;
    if (n >= NN) return;
    int s = g_rowstart[n];
    int e = g_rowstart[n + 1];

    float4 acc = make_float4(0.f, 0.f, 0.f, 0.f);
    h2acc4(acc, *(const uint2*)&g_hs1h[(long)n * 64 + lane * 2]);  // self-loop

    for (int base = s; base < e; base += 32) {
        int idx = base + lane;
        int myi = (idx < e) ? g_csr[idx] : 0;
        int cnt = min(32, e - base);
        int j = 0;
        for (; j + 8 <= cnt; j += 8) {
            int ss[8];
#pragma unroll
            for (int q = 0; q < 8; q++) ss[q] = __shfl_sync(0xffffffffu, myi, j + q);
            uint2 vv[8];
#pragma unroll
            for (int q = 0; q < 8; q++)
                vv[q] = *(const uint2*)&g_hs1h[(long)ss[q] * 64 + lane * 2];
#pragma unroll
            for (int q = 0; q < 8; q++) h2acc4(acc, vv[q]);
        }
        for (; j < cnt; j++) {
            int s0 = __shfl_sync(0xffffffffu, myi, j);
            h2acc4(acc, *(const uint2*)&g_hs1h[(long)s0 * 64 + lane * 2]);
        }
    }
    float d = g_dinv[n];
    float4 bb = *(const float4*)&b1[lane * 4];
    float4 o;
    o.x = fmaxf(fmaf(d, acc.x, bb.x), 0.0f);
    o.y = fmaxf(fmaf(d, acc.y, bb.y), 0.0f);
    o.z = fmaxf(fmaf(d, acc.z, bb.z), 0.0f);
    o.w = fmaxf(fmaf(d, acc.w, bb.w), 0.0f);
    *(float4*)&g_h[(long)n * 128 + lane * 4] = o;
}

// ---------------- gather2: fp16 rows (64 cols), fp32 accumulation ----------------
__global__ void gather2_k(const float* __restrict__ b2) {
    int gt = blockIdx.x * blockDim.x + threadIdx.x;
    int n = gt >> 5;
    int lane = gt & 31;
    if (n >= NN) return;
    int s = g_rowstart[n];
    int e = g_rowstart[n + 1];

    float2 acc;
    {
        unsigned v = g_hs2h[(long)n * 32 + lane];  // self-loop
        acc = __half22float2(*(__half2*)&v);
    }

    for (int base = s; base < e; base += 32) {
        int idx = base + lane;
        int myi = (idx < e) ? g_csr[idx] : 0;
        int cnt = min(32, e - base);
        int j = 0;
        for (; j + 8 <= cnt; j += 8) {
            int ss[8];
#pragma unroll
            for (int q = 0; q < 8; q++) ss[q] = __shfl_sync(0xffffffffu, myi, j + q);
            unsigned vv[8];
#pragma unroll
            for (int q = 0; q < 8; q++)
                vv[q] = g_hs2h[(long)ss[q] * 32 + lane];
#pragma unroll
            for (int q = 0; q < 8; q++) {
                float2 f = __half22float2(*(__half2*)&vv[q]);
                acc.x += f.x; acc.y += f.y;
            }
        }
        for (; j < cnt; j++) {
            int s0 = __shfl_sync(0xffffffffu, myi, j);
            unsigned v = g_hs2h[(long)s0 * 32 + lane];
            float2 f = __half22float2(*(__half2*)&v);
            acc.x += f.x; acc.y += f.y;
        }
    }
    float d = g_dinv[n];
    float2 bb = *(const float2*)&b2[lane * 2];
    float2 o;
    o.x = fmaf(d, acc.x, bb.x);
    o.y = fmaf(d, acc.y, bb.y);
    __half2 hv = __float22half2_rn(o);
    g_lath[(long)n * 32 + lane] = *(unsigned*)&hv;
}

// ---------------- decoder: fp16 latent ----------------
__global__ void decode_k(const int* __restrict__ pe,
                         const int* __restrict__ ne,
                         float* __restrict__ out) {
    int gt = blockIdx.x * blockDim.x + threadIdx.x;
    int w = gt >> 5;
    int lane = gt & 31;
    if (w >= 2 * EPOS) return;
    int a, b;
    if (w < EPOS) {
        a = pe[w];
        b = pe[EPOS + w];
    } else {
        int k = w - EPOS;
        a = ne[k];
        b = ne[EPOS + k];
    }
    unsigned ua = g_lath[(long)a * 32 + lane];
    unsigned ub = g_lath[(long)b * 32 + lane];
    float2 u = __half22float2(*(__half2*)&ua);
    float2 v = __half22float2(*(__half2*)&ub);
    float s = u.x * v.x + u.y * v.y;
#pragma unroll
    for (int o = 16; o > 0; o >>= 1) s += __shfl_xor_sync(0xffffffffu, s, o);
    if (lane == 0) out[w] = s;
}

// ---------------- launch: fork scan/fill chain concurrent with gemm1 ----------------
extern "C" void kernel_launch(void* const* d_in, const int* in_sizes, int n_in,
                              void* d_out, int out_size) {
    const float* x = (const float*)d_in[0];
    const float* W1 = (const float*)d_in[1];
    const float* b1 = (const float*)d_in[2];
    const float* W2 = (const float*)d_in[3];
    const float* b2 = (const float*)d_in[4];
    const int* ei = (const int*)d_in[5];
    const int* pe = (const int*)d_in[6];
    const int* ne = (const int*)d_in[7];
    float* out = (float*)d_out;

    static cudaStream_t sB = nullptr;
    static cudaEvent_t evF = nullptr, evJ = nullptr;
    if (sB == nullptr) {
        cudaStreamCreateWithFlags(&sB, cudaStreamNonBlocking);
        cudaEventCreateWithFlags(&evF, cudaEventDisableTiming);
        cudaEventCreateWithFlags(&evJ, cudaEventDisableTiming);
    }

    // degree histogram (needed by BOTH branches)
    cnt_init_k<<<(NN + 255) / 256, 256>>>();
    cnt_count_k<<<(EE + 255) / 256, 256>>>(ei);

    // fork: scan+fill on sB (needs only g_cnt); dinv+gemm1 on stream 0
    cudaEventRecord(evF, 0);
    cudaStreamWaitEvent(sB, evF, 0);
    scan_bsum_k<<<NCHUNK, 256, 0, sB>>>();
    scan_boff_k<<<1, 512, 0, sB>>>();
    scan_final_k<<<NCHUNK, 256, 0, sB>>>();
    csr_fill_k<<<(EE + 255) / 256, 256, 0, sB>>>(ei);
    cudaEventRecord(evJ, sB);

    dinv_k<<<(NN + 255) / 256, 256>>>();
    gemm1_k<<<(NN + 63) / 64, 256>>>(x, W1);

    // join: gather1 needs csr_fill + gemm1
    cudaStreamWaitEvent(0, evJ, 0);

    gather1_k<<<(NN * 32 + 255) / 256, 256>>>(b1);
    gemm2_k<<<(NN + 63) / 64, 256>>>(W2);
    gather2_k<<<(NN * 32 + 255) / 256, 256>>>(b2);
    decode_k<<<(2 * EPOS * 32 + 255) / 256, 256>>>(pe, ne, out);
}

// round 14
// speedup vs baseline: 1.3427x; 1.1240x over previous
#include <cuda_runtime.h>
#include <cuda_fp16.h>
#include <mma.h>

using namespace nvcuda;

#define NN 100000
#define FF 128
#define HH 128
#define ZZ 64
#define EE 1600000
#define EPOS 200000
#define NCHUNK ((NN + 255) / 256)   // 391

// ---- scratch (static device globals) ----
__device__ __align__(16) int      g_cnt[NN];
__device__ __align__(16) int      g_bsum[512];
__device__ __align__(16) int      g_boff[512];
__device__ __align__(16) int      g_rowstart[NN + 1];
__device__ __align__(16) int      g_cursor[NN];
__device__ __align__(16) int      g_csr[EE];
__device__ __align__(16) float    g_dinv[NN];
__device__ __align__(16) unsigned g_hs1h[NN * 64];   // (x@W1)*dinv as half2 (128 cols)
__device__ __align__(16) unsigned g_hh[NN * 64];     // relu output as half2 (128 cols)
__device__ __align__(16) unsigned g_hs2h[NN * 32];   // (h@W2)*dinv as half2 (64 cols)
__device__ __align__(16) unsigned g_lath[NN * 32];   // latent as half2 (64 cols)

// ---------------- histogram / dinv ----------------
__global__ void cnt_init_k() {
    int i = blockIdx.x * blockDim.x + threadIdx.x;
    if (i < NN) g_cnt[i] = 0;
}

__global__ void cnt_count_k(const int* __restrict__ ei) {
    int e = blockIdx.x * blockDim.x + threadIdx.x;
    if (e < EE) atomicAdd(&g_cnt[ei[EE + e]], 1);
}

__global__ void dinv_k() {
    int i = blockIdx.x * blockDim.x + threadIdx.x;
    if (i < NN) g_dinv[i] = rsqrtf((float)(g_cnt[i] + 1));
}

// ---------------- scan (3 small kernels) ----------------
__global__ void scan_bsum_k() {
    __shared__ int sh[256];
    int i = blockIdx.x * 256 + threadIdx.x;
    sh[threadIdx.x] = (i < NN) ? g_cnt[i] : 0;
    __syncthreads();
    for (int o = 128; o > 0; o >>= 1) {
        if (threadIdx.x < o) sh[threadIdx.x] += sh[threadIdx.x + o];
        __syncthreads();
    }
    if (threadIdx.x == 0) g_bsum[blockIdx.x] = sh[0];
}

__global__ void scan_boff_k() {
    __shared__ int sh[512];
    int t = threadIdx.x;
    int v = (t < NCHUNK) ? g_bsum[t] : 0;
    sh[t] = v;
    __syncthreads();
    for (int o = 1; o < 512; o <<= 1) {
        int add = (t >= o) ? sh[t - o] : 0;
        __syncthreads();
        sh[t] += add;
        __syncthreads();
    }
    g_boff[t] = sh[t] - v;
}

__global__ void scan_final_k() {
    __shared__ int sh[256];
    int t = threadIdx.x;
    int i = blockIdx.x * 256 + t;
    int v = (i < NN) ? g_cnt[i] : 0;
    sh[t] = v;
    __syncthreads();
    for (int o = 1; o < 256; o <<= 1) {
        int add = (t >= o) ? sh[t - o] : 0;
        __syncthreads();
        sh[t] += add;
        __syncthreads();
    }
    if (i < NN) {
        int rs = g_boff[blockIdx.x] + sh[t] - v;
        g_rowstart[i] = rs;
        g_cursor[i] = rs;
        if (i == NN - 1) g_rowstart[NN] = EE;
    }
}

__global__ void csr_fill_k(const int* __restrict__ ei) {
    int e = blockIdx.x * blockDim.x + threadIdx.x;
    if (e < EE) {
        int dst = ei[EE + e];
        int pos = atomicAdd(&g_cursor[dst], 1);
        g_csr[pos] = ei[e];
    }
}

// ---------------- wmma GEMM: out = half2( (X @ W) * dinv[row] ) ----------------
// K fixed at 128. Block = 64 rows x NC cols, 256 threads = 8 warps.
// Warp (rw, cw): rows [rw*16, rw*16+16), cols [cw*NC/2, ...), NT 16x16 n-tiles.
// X converted to fp16 in smem (full K); W loaded in two 64-k halves.
template <int NC, bool XHALF>
__device__ __forceinline__ void wgemm_body(const void* __restrict__ Xv,
                                           const float* __restrict__ W,
                                           unsigned* __restrict__ outh) {
    constexpr int XS = 136;                 // Xh row stride (halves), 16B-aligned rows
    constexpr int WS = NC + 8;              // Wh row stride (halves)
    constexpr int CS = NC + 4;              // Cs row stride (floats)
    constexpr int NH = NC / 2;              // half2 words per output row
    constexpr int NT = NC / 32;             // n-tiles per warp (4 or 2)
    constexpr int SM_A = 64 * XS * 2;       // 17408 B
    constexpr int SM_AB = SM_A + 64 * WS * 2;
    constexpr int SM_EPI = 64 * CS * 4;
    constexpr int SM_TOT = (SM_AB > SM_EPI) ? SM_AB : SM_EPI;
    __shared__ __align__(16) char sm[SM_TOT];
    half* Xh = (half*)sm;
    half* Wh = (half*)(sm + SM_A);
    float* Cs = (float*)sm;                  // aliases Xh/Wh post-compute

    const int tid = threadIdx.x;
    const int row0 = blockIdx.x * 64;
    const int wid = tid >> 5;
    const int rw = wid >> 1;                 // 0..3 row tile
    const int cw = wid & 1;                  // 0..1 col half

    // stage X tile [64][128] -> fp16 smem
    if (XHALF) {
        const unsigned* Xs = (const unsigned*)Xv;   // half2 words, 64/row
        for (int idx = tid; idx < 64 * 64; idx += 256) {
            int r = idx >> 6, c2 = idx & 63;
            int gr = row0 + r;
            unsigned v = (gr < NN) ? Xs[(long)gr * 64 + c2] : 0u;
            *(unsigned*)&Xh[r * XS + 2 * c2] = v;
        }
    } else {
        const float* Xf = (const float*)Xv;
        for (int idx = tid; idx < 64 * 64; idx += 256) {
            int r = idx >> 6, c2 = idx & 63;
            int gr = row0 + r;
            float2 v = (gr < NN) ? *(const float2*)&Xf[(long)gr * 128 + 2 * c2]
                                 : make_float2(0.f, 0.f);
            __half2 h = __float22half2_rn(v);
            *(unsigned*)&Xh[r * XS + 2 * c2] = *(unsigned*)&h;
        }
    }

    wmma::fragment<wmma::accumulator, 16, 16, 16, float> acc[NT];
#pragma unroll
    for (int t = 0; t < NT; t++) wmma::fill_fragment(acc[t], 0.0f);

    for (int kb = 0; kb < 128; kb += 64) {
        // stage W rows [kb, kb+64) -> fp16 smem
        for (int idx = tid; idx < 64 * NH; idx += 256) {
            int kr = idx / NH, c2 = idx % NH;
            float2 v = *(const float2*)&W[(long)(kb + kr) * NC + 2 * c2];
            __half2 h = __float22half2_rn(v);
            *(unsigned*)&Wh[kr * WS + 2 * c2] = *(unsigned*)&h;
        }
        __syncthreads();
#pragma unroll
        for (int k0 = 0; k0 < 64; k0 += 16) {
            wmma::fragment<wmma::matrix_a, 16, 16, 16, half, wmma::row_major> af;
            wmma::load_matrix_sync(af, &Xh[(rw * 16) * XS + kb + k0], XS);
#pragma unroll
            for (int t = 0; t < NT; t++) {
                wmma::fragment<wmma::matrix_b, 16, 16, 16, half, wmma::row_major> bf;
                wmma::load_matrix_sync(bf, &Wh[k0 * WS + cw * NH + t * 16], WS);
                wmma::mma_sync(acc[t], af, bf, acc[t]);
            }
        }
        __syncthreads();
    }

    // epilogue: stage fp32, scale by dinv[row], emit half2
#pragma unroll
    for (int t = 0; t < NT; t++)
        wmma::store_matrix_sync(&Cs[(rw * 16) * CS + cw * NH + t * 16], acc[t],
                                CS, wmma::mem_row_major);
    __syncthreads();
    for (int idx = tid; idx < 64 * NH; idx += 256) {
        int r = idx / NH, c2 = idx % NH;
        int gr = row0 + r;
        if (gr < NN) {
            float s = g_dinv[gr];
            float2 v = make_float2(Cs[r * CS + 2 * c2] * s,
                                   Cs[r * CS + 2 * c2 + 1] * s);
            __half2 h = __float22half2_rn(v);
            outh[(long)gr * NH + c2] = *(unsigned*)&h;
        }
    }
}

__global__ void __launch_bounds__(256) gemm1_k(const float* __restrict__ x,
                                               const float* __restrict__ W1) {
    wgemm_body<HH, false>(x, W1, g_hs1h);
}
__global__ void __launch_bounds__(256) gemm2_k(const float* __restrict__ W2) {
    wgemm_body<ZZ, true>(g_hh, W2, g_hs2h);
}

// ---------------- gather1: fp16 rows (128 cols), fp32 accumulation ----------------
__device__ __forceinline__ void h2acc4(float4& acc, uint2 v) {
    float2 lo = __half22float2(*(__half2*)&v.x);
    float2 hi = __half22float2(*(__half2*)&v.y);
    acc.x += lo.x; acc.y += lo.y; acc.z += hi.x; acc.w += hi.y;
}

__global__ void gather1_k(const float* __restrict__ b1) {
    int gt = blockIdx.x * blockDim.x + threadIdx.x;
    int n = gt >> 5;
    int lane = gt & 31;
    if (n >= NN) return;
    int s = g_rowstart[n];
    int e = g_rowstart[n + 1];

    float4 acc = make_float4(0.f, 0.f, 0.f, 0.f);
    h2acc4(acc, *(const uint2*)&g_hs1h[(long)n * 64 + lane * 2]);  // self-loop

    for (int base = s; base < e; base += 32) {
        int idx = base + lane;
        int myi = (idx < e) ? g_csr[idx] : 0;
        int cnt = min(32, e - base);
        int j = 0;
        for (; j + 8 <= cnt; j += 8) {
            int ss[8];
#pragma unroll
            for (int q = 0; q < 8; q++) ss[q] = __shfl_sync(0xffffffffu, myi, j + q);
            uint2 vv[8];
#pragma unroll
            for (int q = 0; q < 8; q++)
                vv[q] = *(const uint2*)&g_hs1h[(long)ss[q] * 64 + lane * 2];
#pragma unroll
            for (int q = 0; q < 8; q++) h2acc4(acc, vv[q]);
        }
        for (; j < cnt; j++) {
            int s0 = __shfl_sync(0xffffffffu, myi, j);
            h2acc4(acc, *(const uint2*)&g_hs1h[(long)s0 * 64 + lane * 2]);
        }
    }
    float d = g_dinv[n];
    float4 bb = *(const float4*)&b1[lane * 4];
    float4 o;
    o.x = fmaxf(fmaf(d, acc.x, bb.x), 0.0f);
    o.y = fmaxf(fmaf(d, acc.y, bb.y), 0.0f);
    o.z = fmaxf(fmaf(d, acc.z, bb.z), 0.0f);
    o.w = fmaxf(fmaf(d, acc.w, bb.w), 0.0f);
    __half2 h0 = __float22half2_rn(make_float2(o.x, o.y));
    __half2 h1 = __float22half2_rn(make_float2(o.z, o.w));
    *(uint2*)&g_hh[(long)n * 64 + lane * 2] =
        make_uint2(*(unsigned*)&h0, *(unsigned*)&h1);
}

// ---------------- gather2: fp16 rows (64 cols), fp32 accumulation ----------------
__global__ void gather2_k(const float* __restrict__ b2) {
    int gt = blockIdx.x * blockDim.x + threadIdx.x;
    int n = gt >> 5;
    int lane = gt & 31;
    if (n >= NN) return;
    int s = g_rowstart[n];
    int e = g_rowstart[n + 1];

    float2 acc;
    {
        unsigned v = g_hs2h[(long)n * 32 + lane];  // self-loop
        acc = __half22float2(*(__half2*)&v);
    }

    for (int base = s; base < e; base += 32) {
        int idx = base + lane;
        int myi = (idx < e) ? g_csr[idx] : 0;
        int cnt = min(32, e - base);
        int j = 0;
        for (; j + 8 <= cnt; j += 8) {
            int ss[8];
#pragma unroll
            for (int q = 0; q < 8; q++) ss[q] = __shfl_sync(0xffffffffu, myi, j + q);
            unsigned vv[8];
#pragma unroll
            for (int q = 0; q < 8; q++)
                vv[q] = g_hs2h[(long)ss[q] * 32 + lane];
#pragma unroll
            for (int q = 0; q < 8; q++) {
                float2 f = __half22float2(*(__half2*)&vv[q]);
                acc.x += f.x; acc.y += f.y;
            }
        }
        for (; j < cnt; j++) {
            int s0 = __shfl_sync(0xffffffffu, myi, j);
            unsigned v = g_hs2h[(long)s0 * 32 + lane];
            float2 f = __half22float2(*(__half2*)&v);
            acc.x += f.x; acc.y += f.y;
        }
    }
    float d = g_dinv[n];
    float2 bb = *(const float2*)&b2[lane * 2];
    float2 o;
    o.x = fmaf(d, acc.x, bb.x);
    o.y = fmaf(d, acc.y, bb.y);
    __half2 hv = __float22half2_rn(o);
    g_lath[(long)n * 32 + lane] = *(unsigned*)&hv;
}

// ---------------- decoder: fp16 latent ----------------
__global__ void decode_k(const int* __restrict__ pe,
                         const int* __restrict__ ne,
                         float* __restrict__ out) {
    int gt = blockIdx.x * blockDim.x + threadIdx.x;
    int w = gt >> 5;
    int lane = gt & 31;
    if (w >= 2 * EPOS) return;
    int a, b;
    if (w < EPOS) {
        a = pe[w];
        b = pe[EPOS + w];
    } else {
        int k = w - EPOS;
        a = ne[k];
        b = ne[EPOS + k];
    }
    unsigned ua = g_lath[(long)a * 32 + lane];
    unsigned ub = g_lath[(long)b * 32 + lane];
    float2 u = __half22float2(*(__half2*)&ua);
    float2 v = __half22float2(*(__half2*)&ub);
    float s = u.x * v.x + u.y * v.y;
#pragma unroll
    for (int o = 16; o > 0; o >>= 1) s += __shfl_xor_sync(0xffffffffu, s, o);
    if (lane == 0) out[w] = s;
}

// ---------------- launch: fork scan/fill chain concurrent with gemm1 ----------------
extern "C" void kernel_launch(void* const* d_in, const int* in_sizes, int n_in,
                              void* d_out, int out_size) {
    const float* x = (const float*)d_in[0];
    const float* W1 = (const float*)d_in[1];
    const float* b1 = (const float*)d_in[2];
    const float* W2 = (const float*)d_in[3];
    const float* b2 = (const float*)d_in[4];
    const int* ei = (const int*)d_in[5];
    const int* pe = (const int*)d_in[6];
    const int* ne = (const int*)d_in[7];
    float* out = (float*)d_out;

    static cudaStream_t sB = nullptr;
    static cudaEvent_t evF = nullptr, evJ = nullptr;
    if (sB == nullptr) {
        cudaStreamCreateWithFlags(&sB, cudaStreamNonBlocking);
        cudaEventCreateWithFlags(&evF, cudaEventDisableTiming);
        cudaEventCreateWithFlags(&evJ, cudaEventDisableTiming);
    }

    // degree histogram (needed by BOTH branches)
    cnt_init_k<<<(NN + 255) / 256, 256>>>();
    cnt_count_k<<<(EE + 255) / 256, 256>>>(ei);

    // fork: scan+fill on sB (needs only g_cnt); dinv+gemm1 on stream 0
    cudaEventRecord(evF, 0);
    cudaStreamWaitEvent(sB, evF, 0);
    scan_bsum_k<<<NCHUNK, 256, 0, sB>>>();
    scan_boff_k<<<1, 512, 0, sB>>>();
    scan_final_k<<<NCHUNK, 256, 0, sB>>>();
    csr_fill_k<<<(EE + 255) / 256, 256, 0, sB>>>(ei);
    cudaEventRecord(evJ, sB);

    dinv_k<<<(NN + 255) / 256, 256>>>();
    gemm1_k<<<(NN + 63) / 64, 256>>>(x, W1);

    // join: gather1 needs csr_fill + gemm1
    cudaStreamWaitEvent(0, evJ, 0);

    gather1_k<<<(NN * 32 + 255) / 256, 256>>>(b1);
    gemm2_k<<<(NN + 63) / 64, 256>>>(W2);
    gather2_k<<<(NN * 32 + 255) / 256, 256>>>(b2);
    decode_k<<<(2 * EPOS * 32 + 255) / 256, 256>>>(pe, ne, out);
}